// round 4
// baseline (speedup 1.0000x reference)
#include <cuda_runtime.h>

#define T_LEN 4096
#define BATCH 8
#define DIM   256
#define PDIM  256
#define NP3   768

// Scratch (static device globals: allocation-guard-safe)
__device__ float g_q[BATCH * T_LEN * PDIM];     // [b][t][p], pre-scaled by P^-0.5
__device__ float g_k[BATCH * T_LEN * PDIM];     // [b][t][p]
__device__ float g_v[BATCH * T_LEN * PDIM];     // [b][t][p]
__device__ float g_attn[T_LEN * BATCH * PDIM];  // [t][b][p]

// ---------------------------------------------------------------------------
// Kernel 1: QKV projection.  X[32768,256] @ W[256,768] + b -> route q/k/v.
// BM=BN=64, BK=16, 256 threads, 4x4 register tile.
// ---------------------------------------------------------------------------
__global__ __launch_bounds__(256) void qkv_kernel(const float* __restrict__ X,
                                                  const float* __restrict__ W,
                                                  const float* __restrict__ bias) {
    __shared__ float As[16][65];  // transposed A tile: As[k][m]
    __shared__ float Bs[16][64];  // natural B tile:    Bs[k][n]

    const int tid = threadIdx.x;
    const int tx = tid & 15, ty = tid >> 4;
    const int row0 = blockIdx.y * 64;
    const int col0 = blockIdx.x * 64;

    float acc[4][4] = {};

    const int arow = tid >> 2, acg = (tid & 3) * 4;   // A: 64 rows x 16 cols
    const int brow = tid >> 4, bcg = (tid & 15) * 4;  // B: 16 rows x 64 cols

    for (int k0 = 0; k0 < DIM; k0 += 16) {
        float4 a = *(const float4*)(X + (row0 + arow) * DIM + k0 + acg);
        As[acg + 0][arow] = a.x;
        As[acg + 1][arow] = a.y;
        As[acg + 2][arow] = a.z;
        As[acg + 3][arow] = a.w;
        *(float4*)&Bs[brow][bcg] = *(const float4*)(W + (k0 + brow) * NP3 + col0 + bcg);
        __syncthreads();

        #pragma unroll
        for (int kk = 0; kk < 16; ++kk) {
            float av[4], bv[4];
            #pragma unroll
            for (int i = 0; i < 4; ++i) av[i] = As[kk][ty * 4 + i];
            float4 b4 = *(const float4*)&Bs[kk][tx * 4];
            bv[0] = b4.x; bv[1] = b4.y; bv[2] = b4.z; bv[3] = b4.w;
            #pragma unroll
            for (int i = 0; i < 4; ++i)
                #pragma unroll
                for (int j = 0; j < 4; ++j)
                    acc[i][j] += av[i] * bv[j];
        }
        __syncthreads();
    }

    #pragma unroll
    for (int i = 0; i < 4; ++i) {
        const int m = row0 + ty * 4 + i;
        const int t = m >> 3, b = m & 7;
        const int base = (b * T_LEN + t) * PDIM;
        #pragma unroll
        for (int j = 0; j < 4; ++j) {
            const int n = col0 + tx * 4 + j;
            const float val = acc[i][j] + bias[n];
            if (n < 256)      g_q[base + n]       = val * 0.0625f;  // 256^-0.5
            else if (n < 512) g_k[base + n - 256] = val;
            else              g_v[base + n - 512] = val;
        }
    }
}

// ---------------------------------------------------------------------------
// Kernel 2: flash attention.  One block = (batch bb, 64 query rows).
// smem: qs[256][65] (transposed), Ks[256][65] (transposed), Vs[64][256],
//       Ps[64][68].  256 threads as 16x16; S-tile 4x4/thread, O-tile 4x16.
// ---------------------------------------------------------------------------
#define ATTN_SMEM_FLOATS (256 * 65 + 256 * 65 + 64 * 256 + 64 * 68)
#define ATTN_SMEM_BYTES  (ATTN_SMEM_FLOATS * 4)

__global__ __launch_bounds__(256, 1) void attn_kernel() {
    extern __shared__ float sm[];
    float* qs = sm;                       // [256][65]  qs[d*65 + row]
    float* Ks = sm + 256 * 65;            // [256][65]  Ks[d*65 + col]
    float* Vs = Ks + 256 * 65;            // [64][256]  Vs[s*256 + c]
    float* Ps = Vs + 64 * 256;            // [64][68]   Ps[row*68 + col]

    const int tid = threadIdx.x;
    const int tx = tid & 15, ty = tid >> 4;
    const int t0 = blockIdx.x * 64;
    const int bb = blockIdx.y;

    // Load q tile transposed into smem
    for (int it = 0; it < 16; ++it) {
        const int idx = it * 256 + tid;
        const int r = idx >> 6, d4 = idx & 63;
        float4 v = *(const float4*)(g_q + (bb * T_LEN + t0 + r) * PDIM + d4 * 4);
        const int dd = d4 * 4;
        qs[(dd + 0) * 65 + r] = v.x;
        qs[(dd + 1) * 65 + r] = v.y;
        qs[(dd + 2) * 65 + r] = v.z;
        qs[(dd + 3) * 65 + r] = v.w;
    }

    float m_i[4], l_i[4], acc[4][16];
    #pragma unroll
    for (int i = 0; i < 4; ++i) {
        m_i[i] = -1e30f;
        l_i[i] = 0.0f;
        #pragma unroll
        for (int c = 0; c < 16; ++c) acc[i][c] = 0.0f;
    }

    for (int s0 = 0; s0 < T_LEN; s0 += 64) {
        __syncthreads();  // prior PV done before Ks/Vs overwrite
        // Load K tile (transposed) and V tile (natural)
        for (int it = 0; it < 16; ++it) {
            const int idx = it * 256 + tid;
            const int r = idx >> 6, d4 = idx & 63;
            const int goff = (bb * T_LEN + s0 + r) * PDIM + d4 * 4;
            float4 kv = *(const float4*)(g_k + goff);
            const int dd = d4 * 4;
            Ks[(dd + 0) * 65 + r] = kv.x;
            Ks[(dd + 1) * 65 + r] = kv.y;
            Ks[(dd + 2) * 65 + r] = kv.z;
            Ks[(dd + 3) * 65 + r] = kv.w;
            *(float4*)(Vs + r * 256 + d4 * 4) = *(const float4*)(g_v + goff);
        }
        __syncthreads();

        // S = q @ K^T  (64x64 tile, 4x4 per thread)
        float sv[4][4] = {};
        const float* qp = qs + ty * 4;
        const float* kp = Ks + tx * 4;
        #pragma unroll 4
        for (int d = 0; d < 256; ++d) {
            float av[4], bv[4];
            #pragma unroll
            for (int i = 0; i < 4; ++i) av[i] = qp[d * 65 + i];
            #pragma unroll
            for (int j = 0; j < 4; ++j) bv[j] = kp[d * 65 + j];
            #pragma unroll
            for (int i = 0; i < 4; ++i)
                #pragma unroll
                for (int j = 0; j < 4; ++j)
                    sv[i][j] += av[i] * bv[j];
        }

        // Online softmax per row (row spread over 16 tx lanes in same half-warp)
        #pragma unroll
        for (int i = 0; i < 4; ++i) {
            float mx = fmaxf(fmaxf(sv[i][0], sv[i][1]), fmaxf(sv[i][2], sv[i][3]));
            #pragma unroll
            for (int off = 1; off < 16; off <<= 1)
                mx = fmaxf(mx, __shfl_xor_sync(0xffffffffu, mx, off));
            const float mn = fmaxf(m_i[i], mx);
            const float alpha = __expf(m_i[i] - mn);
            float p[4];
            float rs = 0.0f;
            #pragma unroll
            for (int j = 0; j < 4; ++j) { p[j] = __expf(sv[i][j] - mn); rs += p[j]; }
            #pragma unroll
            for (int off = 1; off < 16; off <<= 1)
                rs += __shfl_xor_sync(0xffffffffu, rs, off);
            l_i[i] = l_i[i] * alpha + rs;
            m_i[i] = mn;
            #pragma unroll
            for (int c = 0; c < 16; ++c) acc[i][c] *= alpha;
            float* pr = Ps + (ty * 4 + i) * 68 + tx * 4;
            pr[0] = p[0]; pr[1] = p[1]; pr[2] = p[2]; pr[3] = p[3];
        }
        __syncthreads();

        // O += P @ V  (4x16 per thread)
        const float4* V4 = (const float4*)Vs;
        #pragma unroll 2
        for (int s = 0; s < 64; ++s) {
            float pv[4];
            #pragma unroll
            for (int i = 0; i < 4; ++i) pv[i] = Ps[(ty * 4 + i) * 68 + s];
            float vv[16];
            #pragma unroll
            for (int q = 0; q < 4; ++q) {
                float4 v4 = V4[s * 64 + tx * 4 + q];
                vv[q * 4 + 0] = v4.x; vv[q * 4 + 1] = v4.y;
                vv[q * 4 + 2] = v4.z; vv[q * 4 + 3] = v4.w;
            }
            #pragma unroll
            for (int i = 0; i < 4; ++i)
                #pragma unroll
                for (int c = 0; c < 16; ++c)
                    acc[i][c] += pv[i] * vv[c];
        }
    }

    // Epilogue: normalize, write [t][b][p]
    #pragma unroll
    for (int i = 0; i < 4; ++i) {
        const float inv = 1.0f / l_i[i];
        const int t = t0 + ty * 4 + i;
        float* orow = g_attn + (t * BATCH + bb) * PDIM + tx * 16;
        #pragma unroll
        for (int q = 0; q < 4; ++q) {
            float4 o;
            o.x = acc[i][q * 4 + 0] * inv;
            o.y = acc[i][q * 4 + 1] * inv;
            o.z = acc[i][q * 4 + 2] * inv;
            o.w = acc[i][q * 4 + 3] * inv;
            *(float4*)(orow + q * 4) = o;
        }
    }
}

// ---------------------------------------------------------------------------
// Kernel 3: output projection.  g_attn[32768,256] @ W_out[256,256] + b_out.
// ---------------------------------------------------------------------------
__global__ __launch_bounds__(256) void out_kernel(const float* __restrict__ W,
                                                  const float* __restrict__ bias,
                                                  float* __restrict__ out) {
    __shared__ float As[16][65];
    __shared__ float Bs[16][64];

    const int tid = threadIdx.x;
    const int tx = tid & 15, ty = tid >> 4;
    const int row0 = blockIdx.y * 64;
    const int col0 = blockIdx.x * 64;

    float acc[4][4] = {};

    const int arow = tid >> 2, acg = (tid & 3) * 4;
    const int brow = tid >> 4, bcg = (tid & 15) * 4;

    for (int k0 = 0; k0 < PDIM; k0 += 16) {
        float4 a = *(const float4*)(g_attn + (row0 + arow) * PDIM + k0 + acg);
        As[acg + 0][arow] = a.x;
        As[acg + 1][arow] = a.y;
        As[acg + 2][arow] = a.z;
        As[acg + 3][arow] = a.w;
        *(float4*)&Bs[brow][bcg] = *(const float4*)(W + (k0 + brow) * PDIM + col0 + bcg);
        __syncthreads();

        #pragma unroll
        for (int kk = 0; kk < 16; ++kk) {
            float av[4], bv[4];
            #pragma unroll
            for (int i = 0; i < 4; ++i) av[i] = As[kk][ty * 4 + i];
            float4 b4 = *(const float4*)&Bs[kk][tx * 4];
            bv[0] = b4.x; bv[1] = b4.y; bv[2] = b4.z; bv[3] = b4.w;
            #pragma unroll
            for (int i = 0; i < 4; ++i)
                #pragma unroll
                for (int j = 0; j < 4; ++j)
                    acc[i][j] += av[i] * bv[j];
        }
        __syncthreads();
    }

    #pragma unroll
    for (int i = 0; i < 4; ++i) {
        const int m = row0 + ty * 4 + i;
        const int n = col0 + tx * 4;
        float4 bb4 = *(const float4*)(bias + n);
        float4 o;
        o.x = acc[i][0] + bb4.x;
        o.y = acc[i][1] + bb4.y;
        o.z = acc[i][2] + bb4.z;
        o.w = acc[i][3] + bb4.w;
        *(float4*)(out + m * PDIM + n) = o;
    }
}

// ---------------------------------------------------------------------------
extern "C" void kernel_launch(void* const* d_in, const int* in_sizes, int n_in,
                              void* d_out, int out_size) {
    const float* query = (const float*)d_in[0];  // [4096, 8, 256]
    const float* W_kqv = (const float*)d_in[1];  // [256, 768]
    const float* b_kqv = (const float*)d_in[2];  // [768]
    const float* W_out = (const float*)d_in[3];  // [256, 256]
    const float* b_out = (const float*)d_in[4];  // [256]
    float* out = (float*)d_out;                  // [4096, 8, 256]

    qkv_kernel<<<dim3(NP3 / 64, (T_LEN * BATCH) / 64), 256>>>(query, W_kqv, b_kqv);

    cudaFuncSetAttribute(attn_kernel, cudaFuncAttributeMaxDynamicSharedMemorySize,
                         ATTN_SMEM_BYTES);
    attn_kernel<<<dim3(T_LEN / 64, BATCH), 256, ATTN_SMEM_BYTES>>>();

    out_kernel<<<dim3(PDIM / 64, (T_LEN * BATCH) / 64), 256>>>(W_out, b_out, out);
}

// round 7
// speedup vs baseline: 4.3779x; 4.3779x over previous
#include <cuda_runtime.h>
#include <cuda_bf16.h>

#define T_LEN 4096
#define BATCH 8
#define DIM   256
#define PDIM  256
#define NP3   768

// ---------------------------------------------------------------------------
// Global scratch (static __device__: allocation-guard-safe).
// q/k/v stored row-major [b][t][256] as bf16 hi/lo pairs (q pre-scaled 1/16).
// ---------------------------------------------------------------------------
__device__ __nv_bfloat16 g_qh[8388608], g_ql[8388608];
__device__ __nv_bfloat16 g_kh[8388608], g_kl[8388608];
__device__ __nv_bfloat16 g_vh[8388608], g_vl[8388608];
__device__ float g_attn[T_LEN * BATCH * PDIM];  // [t][b][p]

__device__ __forceinline__ void bsplit(float x, __nv_bfloat16& h, __nv_bfloat16& l) {
    h = __float2bfloat16(x);
    l = __float2bfloat16(x - __bfloat162float(h));
}

// ---------------------------------------------------------------------------
// Kernel 1: QKV projection (fp32 SIMT, proven) -> bf16 hi/lo row-major.
// ---------------------------------------------------------------------------
__global__ __launch_bounds__(256) void qkv_kernel(const float* __restrict__ X,
                                                  const float* __restrict__ W,
                                                  const float* __restrict__ bias) {
    __shared__ float As[16][65];
    __shared__ float Bs[16][64];

    const int tid = threadIdx.x;
    const int tx = tid & 15, ty = tid >> 4;
    const int row0 = blockIdx.y * 64;
    const int col0 = blockIdx.x * 64;

    float acc[4][4] = {};
    const int arow = tid >> 2, acg = (tid & 3) * 4;
    const int brow = tid >> 4, bcg = (tid & 15) * 4;

    for (int k0 = 0; k0 < DIM; k0 += 16) {
        float4 a = *(const float4*)(X + (row0 + arow) * DIM + k0 + acg);
        As[acg + 0][arow] = a.x;
        As[acg + 1][arow] = a.y;
        As[acg + 2][arow] = a.z;
        As[acg + 3][arow] = a.w;
        *(float4*)&Bs[brow][bcg] = *(const float4*)(W + (k0 + brow) * NP3 + col0 + bcg);
        __syncthreads();
        #pragma unroll
        for (int kk = 0; kk < 16; ++kk) {
            float av[4], bv[4];
            #pragma unroll
            for (int i = 0; i < 4; ++i) av[i] = As[kk][ty * 4 + i];
            float4 b4 = *(const float4*)&Bs[kk][tx * 4];
            bv[0] = b4.x; bv[1] = b4.y; bv[2] = b4.z; bv[3] = b4.w;
            #pragma unroll
            for (int i = 0; i < 4; ++i)
                #pragma unroll
                for (int j = 0; j < 4; ++j)
                    acc[i][j] += av[i] * bv[j];
        }
        __syncthreads();
    }

    #pragma unroll
    for (int i = 0; i < 4; ++i) {
        const int m = row0 + ty * 4 + i;
        const int t = m >> 3, b = m & 7;
        #pragma unroll
        for (int jp = 0; jp < 4; jp += 2) {
            const int n = col0 + tx * 4 + jp;
            float v0 = acc[i][jp] + bias[n];
            float v1 = acc[i][jp + 1] + bias[n + 1];
            __nv_bfloat16* gh;
            __nv_bfloat16* gl;
            int c;
            if (n < 256)      { gh = g_qh; gl = g_ql; c = n;       v0 *= 0.0625f; v1 *= 0.0625f; }
            else if (n < 512) { gh = g_kh; gl = g_kl; c = n - 256; }
            else              { gh = g_vh; gl = g_vl; c = n - 512; }
            const size_t idx = (size_t)(b * T_LEN + t) * 256 + c;
            __nv_bfloat16 h0, l0, h1, l1;
            bsplit(v0, h0, l0);
            bsplit(v1, h1, l1);
            __nv_bfloat162 hh; hh.x = h0; hh.y = h1;
            __nv_bfloat162 ll; ll.x = l0; ll.y = l1;
            *(__nv_bfloat162*)(gh + idx) = hh;
            *(__nv_bfloat162*)(gl + idx) = ll;
        }
    }
}

// ---------------------------------------------------------------------------
// mma.sync / ldmatrix / cp.async helpers (baseline ISA: compiles at compute_103)
// ---------------------------------------------------------------------------
__device__ __forceinline__ unsigned s2u(const void* p) {
    unsigned a;
    asm("{ .reg .u64 t; cvta.to.shared.u64 t, %1; cvt.u32.u64 %0, t; }" : "=r"(a) : "l"(p));
    return a;
}

#define MMA(d, a, b0, b1) \
    asm volatile( \
        "mma.sync.aligned.m16n8k16.row.col.f32.bf16.bf16.f32 " \
        "{%0,%1,%2,%3},{%4,%5,%6,%7},{%8,%9},{%0,%1,%2,%3};" \
        : "+f"((d)[0]), "+f"((d)[1]), "+f"((d)[2]), "+f"((d)[3]) \
        : "r"((a)[0]), "r"((a)[1]), "r"((a)[2]), "r"((a)[3]), "r"(b0), "r"(b1))

#define LDSM4(r, addr) \
    asm volatile("ldmatrix.sync.aligned.m8n8.x4.shared.b16 {%0,%1,%2,%3}, [%4];" \
        : "=r"((r)[0]), "=r"((r)[1]), "=r"((r)[2]), "=r"((r)[3]) : "r"(addr))

#define LDSM4T(r, addr) \
    asm volatile("ldmatrix.sync.aligned.m8n8.x4.trans.shared.b16 {%0,%1,%2,%3}, [%4];" \
        : "=r"((r)[0]), "=r"((r)[1]), "=r"((r)[2]), "=r"((r)[3]) : "r"(addr))

__device__ __forceinline__ void cp16(unsigned d, const void* s) {
    asm volatile("cp.async.cg.shared.global [%0], [%1], 16;" :: "r"(d), "l"(s));
}
#define CP_COMMIT() asm volatile("cp.async.commit_group;" ::: "memory")
#define CP_WAIT1()  asm volatile("cp.async.wait_group 1;" ::: "memory")

// 512-byte rows, XOR-swizzled 16B units (low 3 bits by row&7): conflict-free ldmatrix
__device__ __forceinline__ unsigned swadr512(unsigned base, int r, int cbyte) {
    unsigned u = (unsigned)cbyte >> 4;
    u = (u & 24u) | ((u ^ (unsigned)r) & 7u);
    return base + r * 512 + (u << 4);
}

// smem layout (bytes)
#define SM_QH 0u
#define SM_QL 32768u
#define SM_KH 65536u
#define SM_KL 98304u
#define SM_VH 131072u
#define SM_VL 163840u
#define SM_PH 196608u
#define SM_PL 204800u
#define SM_L  212992u
#define SMEM_TOTAL (SM_L + 256u)   // 213248 B

// Stage one 64x256-bf16 tile (hi+lo) global -> swizzled smem via cp.async.
__device__ __forceinline__ void stage(char* sm, unsigned sbase_h, unsigned sbase_l,
                                      const __nv_bfloat16* gh, const __nv_bfloat16* gl,
                                      int grow0, int tid) {
    for (int c = tid; c < 2048; c += 256) {
        const int row = c >> 5, unit = c & 31;
        const unsigned su = (unsigned)unit ^ ((unsigned)row & 7u);
        const unsigned d = row * 512 + (su << 4);
        const size_t gb = (size_t)(grow0 + row) * 256 + unit * 8;
        cp16(sbase_h + d, gh + gb);
        cp16(sbase_l + d, gl + gb);
    }
}

// ---------------------------------------------------------------------------
// Kernel 2: flash attention, mma.sync bf16x3, no-max softmax.
// CTA: 256 thr / 8 warps; 64 q-rows; loop 64 s-tiles of 64.
// warp w: wm = w>>1 (m16 rows), wn = w&1 (n-half for S, p-half for O).
// ---------------------------------------------------------------------------
__global__ __launch_bounds__(256, 1) void attn_mma_kernel() {
    extern __shared__ char sm[];
    const unsigned sbase = s2u(sm);
    const int tid = threadIdx.x;
    const int warp = tid >> 5, lane = tid & 31;
    const int wm = warp >> 1, wn = warp & 1;
    const int qt = blockIdx.x, bb = blockIdx.y;
    float* l_sm = (float*)(sm + SM_L);

    if (tid < 64) l_sm[tid] = 0.0f;

    const int gq0 = bb * T_LEN + qt * 64;
    const int gk0 = bb * T_LEN;

    // Prologue: group0 = Q + K0, group1 = V0
    stage(sm, sbase + SM_QH, sbase + SM_QL, g_qh, g_ql, gq0, tid);
    stage(sm, sbase + SM_KH, sbase + SM_KL, g_kh, g_kl, gk0, tid);
    CP_COMMIT();
    stage(sm, sbase + SM_VH, sbase + SM_VL, g_vh, g_vl, gk0, tid);
    CP_COMMIT();

    float o[16][4];
    #pragma unroll
    for (int j = 0; j < 16; ++j)
        #pragma unroll
        for (int q = 0; q < 4; ++q) o[j][q] = 0.0f;

    float lsum0 = 0.0f, lsum1 = 0.0f;
    const int r0 = wm * 16 + (lane >> 2);
    const int r1 = r0 + 8;

    for (int st = 0; st < 64; ++st) {
        CP_WAIT1();          // K_st (and Q on st=0) complete; V_st still pending
        __syncthreads();

        // ---- S = Q K^T (bf16x3) ----
        float s[4][4] = {};
        {
            const int ar = wm * 16 + (lane & 15);
            const int koff = (lane & 16) ? 16 : 0;
            #pragma unroll
            for (int ks = 0; ks < 16; ++ks) {
                const int kb = ks * 32 + koff;
                const unsigned aa = swadr512(sbase + SM_QH, ar, kb);
                unsigned qh[4], ql[4];
                LDSM4(qh, aa);
                LDSM4(ql, aa + (SM_QL - SM_QH));
                #pragma unroll
                for (int h = 0; h < 2; ++h) {
                    const int br = wn * 32 + h * 16 + (lane & 15);
                    const unsigned ba = swadr512(sbase + SM_KH, br, kb);
                    unsigned kh[4], kl[4];
                    LDSM4(kh, ba);
                    LDSM4(kl, ba + (SM_KL - SM_KH));
                    MMA(s[2 * h], qh, kh[0], kh[2]);
                    MMA(s[2 * h], qh, kl[0], kl[2]);
                    MMA(s[2 * h], ql, kh[0], kh[2]);
                    MMA(s[2 * h + 1], qh, kh[1], kh[3]);
                    MMA(s[2 * h + 1], qh, kl[1], kl[3]);
                    MMA(s[2 * h + 1], ql, kh[1], kh[3]);
                }
            }
        }

        // ---- P = exp(S) -> smem (hi/lo), accumulate row sums ----
        #pragma unroll
        for (int j = 0; j < 4; ++j) {
            const float p0 = __expf(s[j][0]);
            const float p1 = __expf(s[j][1]);
            const float p2 = __expf(s[j][2]);
            const float p3 = __expf(s[j][3]);
            lsum0 += p0 + p1;
            lsum1 += p2 + p3;
            __nv_bfloat16 h0, l0, h1, l1, h2, l2, h3, l3;
            bsplit(p0, h0, l0); bsplit(p1, h1, l1);
            bsplit(p2, h2, l2); bsplit(p3, h3, l3);
            const unsigned hw01 = ((unsigned)__bfloat16_as_ushort(h1) << 16) | __bfloat16_as_ushort(h0);
            const unsigned hw23 = ((unsigned)__bfloat16_as_ushort(h3) << 16) | __bfloat16_as_ushort(h2);
            const unsigned lw01 = ((unsigned)__bfloat16_as_ushort(l1) << 16) | __bfloat16_as_ushort(l0);
            const unsigned lw23 = ((unsigned)__bfloat16_as_ushort(l3) << 16) | __bfloat16_as_ushort(l2);
            const unsigned u = ((unsigned)(wn * 4 + j) ^ ((unsigned)r0 & 7u)) << 4;
            const unsigned lo4 = (lane & 3) * 4;
            *(unsigned*)(sm + SM_PH + r0 * 128 + u + lo4) = hw01;
            *(unsigned*)(sm + SM_PH + r1 * 128 + u + lo4) = hw23;
            *(unsigned*)(sm + SM_PL + r0 * 128 + u + lo4) = lw01;
            *(unsigned*)(sm + SM_PL + r1 * 128 + u + lo4) = lw23;
        }
        __syncthreads();     // all K reads done; P visible

        if (st < 63)
            stage(sm, sbase + SM_KH, sbase + SM_KL, g_kh, g_kl, gk0 + (st + 1) * 64, tid);
        CP_COMMIT();

        CP_WAIT1();          // V_st complete; K_{st+1} pending
        __syncthreads();

        // ---- O += P V (bf16x3) ----
        {
            const int ar = wm * 16 + (lane & 15);
            #pragma unroll
            for (int ks = 0; ks < 4; ++ks) {
                const int kb = ks * 32 + ((lane & 16) ? 16 : 0);
                const unsigned up = ((unsigned)(kb >> 4) ^ ((unsigned)ar & 7u)) << 4;
                const unsigned pa = sbase + SM_PH + ar * 128 + up;
                unsigned ph[4], pl[4];
                LDSM4(ph, pa);
                LDSM4(pl, pa + (SM_PL - SM_PH));
                const int vr = ks * 16 + (lane & 7) + ((lane & 16) >> 1);
                #pragma unroll
                for (int nb = 0; nb < 8; ++nb) {
                    const int pb = wn * 256 + nb * 32 + ((lane & 8) << 1);
                    const unsigned va = swadr512(sbase + SM_VH, vr, pb);
                    unsigned vh[4], vl[4];
                    LDSM4T(vh, va);
                    LDSM4T(vl, va + (SM_VL - SM_VH));
                    MMA(o[nb * 2], ph, vh[0], vh[2]);
                    MMA(o[nb * 2], ph, vl[0], vl[2]);
                    MMA(o[nb * 2], pl, vh[0], vh[2]);
                    MMA(o[nb * 2 + 1], ph, vh[1], vh[3]);
                    MMA(o[nb * 2 + 1], ph, vl[1], vl[3]);
                    MMA(o[nb * 2 + 1], pl, vh[1], vh[3]);
                }
            }
        }
        __syncthreads();     // all V reads done

        if (st < 63)
            stage(sm, sbase + SM_VH, sbase + SM_VL, g_vh, g_vl, gk0 + (st + 1) * 64, tid);
        CP_COMMIT();
    }

    // ---- l reduction across quad lanes + the two n-warps ----
    lsum0 += __shfl_xor_sync(0xffffffffu, lsum0, 1);
    lsum0 += __shfl_xor_sync(0xffffffffu, lsum0, 2);
    lsum1 += __shfl_xor_sync(0xffffffffu, lsum1, 1);
    lsum1 += __shfl_xor_sync(0xffffffffu, lsum1, 2);
    if ((lane & 3) == 0) {
        atomicAdd(&l_sm[r0], lsum0);
        atomicAdd(&l_sm[r1], lsum1);
    }
    __syncthreads();

    // ---- epilogue: O / l -> g_attn[t][b][p] ----
    const float inv0 = 1.0f / l_sm[r0];
    const float inv1 = 1.0f / l_sm[r1];
    const size_t t0g = (size_t)(qt * 64 + r0) * BATCH + bb;
    const size_t t1g = (size_t)(qt * 64 + r1) * BATCH + bb;
    #pragma unroll
    for (int j = 0; j < 16; ++j) {
        const int cp = wn * 128 + j * 8 + (lane & 3) * 2;
        float2 v0, v1;
        v0.x = o[j][0] * inv0; v0.y = o[j][1] * inv0;
        v1.x = o[j][2] * inv1; v1.y = o[j][3] * inv1;
        *(float2*)(g_attn + t0g * 256 + cp) = v0;
        *(float2*)(g_attn + t1g * 256 + cp) = v1;
    }
}

// ---------------------------------------------------------------------------
// Kernel 3: output projection (unchanged fp32 SIMT).
// ---------------------------------------------------------------------------
__global__ __launch_bounds__(256) void out_kernel(const float* __restrict__ W,
                                                  const float* __restrict__ bias,
                                                  float* __restrict__ out) {
    __shared__ float As[16][65];
    __shared__ float Bs[16][64];

    const int tid = threadIdx.x;
    const int tx = tid & 15, ty = tid >> 4;
    const int row0 = blockIdx.y * 64;
    const int col0 = blockIdx.x * 64;

    float acc[4][4] = {};
    const int arow = tid >> 2, acg = (tid & 3) * 4;
    const int brow = tid >> 4, bcg = (tid & 15) * 4;

    for (int k0 = 0; k0 < PDIM; k0 += 16) {
        float4 a = *(const float4*)(g_attn + (row0 + arow) * PDIM + k0 + acg);
        As[acg + 0][arow] = a.x;
        As[acg + 1][arow] = a.y;
        As[acg + 2][arow] = a.z;
        As[acg + 3][arow] = a.w;
        *(float4*)&Bs[brow][bcg] = *(const float4*)(W + (k0 + brow) * PDIM + col0 + bcg);
        __syncthreads();
        #pragma unroll
        for (int kk = 0; kk < 16; ++kk) {
            float av[4], bv[4];
            #pragma unroll
            for (int i = 0; i < 4; ++i) av[i] = As[kk][ty * 4 + i];
            float4 b4 = *(const float4*)&Bs[kk][tx * 4];
            bv[0] = b4.x; bv[1] = b4.y; bv[2] = b4.z; bv[3] = b4.w;
            #pragma unroll
            for (int i = 0; i < 4; ++i)
                #pragma unroll
                for (int j = 0; j < 4; ++j)
                    acc[i][j] += av[i] * bv[j];
        }
        __syncthreads();
    }

    #pragma unroll
    for (int i = 0; i < 4; ++i) {
        const int m = row0 + ty * 4 + i;
        const int n = col0 + tx * 4;
        float4 bb4 = *(const float4*)(bias + n);
        float4 v;
        v.x = acc[i][0] + bb4.x;
        v.y = acc[i][1] + bb4.y;
        v.z = acc[i][2] + bb4.z;
        v.w = acc[i][3] + bb4.w;
        *(float4*)(out + m * PDIM + n) = v;
    }
}

// ---------------------------------------------------------------------------
extern "C" void kernel_launch(void* const* d_in, const int* in_sizes, int n_in,
                              void* d_out, int out_size) {
    const float* query = (const float*)d_in[0];
    const float* W_kqv = (const float*)d_in[1];
    const float* b_kqv = (const float*)d_in[2];
    const float* W_out = (const float*)d_in[3];
    const float* b_out = (const float*)d_in[4];
    float* out = (float*)d_out;

    qkv_kernel<<<dim3(NP3 / 64, (T_LEN * BATCH) / 64), 256>>>(query, W_kqv, b_kqv);

    cudaFuncSetAttribute(attn_mma_kernel, cudaFuncAttributeMaxDynamicSharedMemorySize,
                         SMEM_TOTAL);
    attn_mma_kernel<<<dim3(T_LEN / 64, BATCH), 256, SMEM_TOTAL>>>();

    out_kernel<<<dim3(PDIM / 64, (T_LEN * BATCH) / 64), 256>>>(W_out, b_out, out);
}